// round 1
// baseline (speedup 1.0000x reference)
#include <cuda_runtime.h>
#include <cstddef>

#define D 1024
#define H 16
#define HD 64
#define S 2048
#define BATCH 2
#define M_ROWS (BATCH * S)        // 4096
#define LN_EPS 1e-5f
#define SM_SCALE (1.0f / 32.0f)   // 1/sqrt(D) = 1/sqrt(1024)

// Scratch (no allocations allowed in kernel_launch)
__device__ float g_qkv[(size_t)M_ROWS * 3 * D];   // 50.3 MB
__device__ float g_o[(size_t)M_ROWS * D];         // 16.8 MB
__device__ float g_y[(size_t)M_ROWS * D];         // 16.8 MB

// ---------------------------------------------------------------------------
// GEMM (NT): C[M,N] = A[M,K] @ Bt[N,K]^T + bias[N] (+ residual[M,N])
// BM=BN=128, BK=16, 256 threads, 8x8 register micro-tile.
// ---------------------------------------------------------------------------
template <bool RESID>
__global__ __launch_bounds__(256)
void gemm_nt(const float* __restrict__ A, const float* __restrict__ Bt,
             const float* __restrict__ bias, const float* __restrict__ resid,
             float* __restrict__ C, int M, int N, int K)
{
    const int BM = 128, BN = 128, BK = 16;
    __shared__ float As[BK][BM];
    __shared__ float Bs[BK][BN];

    const int bm = blockIdx.y * BM;
    const int bn = blockIdx.x * BN;
    const int tid = threadIdx.x;
    const int tr = tid >> 4;     // 0..15
    const int tc = tid & 15;     // 0..15

    float acc[8][8];
    #pragma unroll
    for (int i = 0; i < 8; i++)
        #pragma unroll
        for (int j = 0; j < 8; j++) acc[i][j] = 0.f;

    for (int k0 = 0; k0 < K; k0 += BK) {
        // Load + transpose tiles: 128x16 floats each = 512 float4; 256 thr * 2
        #pragma unroll
        for (int l = 0; l < 2; l++) {
            int f = tid + l * 256;            // 0..511
            int row = f >> 2;                 // 0..127
            int kc = (f & 3) << 2;            // 0,4,8,12
            float4 va = *(const float4*)&A[(size_t)(bm + row) * K + k0 + kc];
            As[kc + 0][row] = va.x; As[kc + 1][row] = va.y;
            As[kc + 2][row] = va.z; As[kc + 3][row] = va.w;
            float4 vb = *(const float4*)&Bt[(size_t)(bn + row) * K + k0 + kc];
            Bs[kc + 0][row] = vb.x; Bs[kc + 1][row] = vb.y;
            Bs[kc + 2][row] = vb.z; Bs[kc + 3][row] = vb.w;
        }
        __syncthreads();

        #pragma unroll
        for (int kk = 0; kk < BK; kk++) {
            float a[8], b[8];
            *(float4*)&a[0] = *(const float4*)&As[kk][tr * 8];
            *(float4*)&a[4] = *(const float4*)&As[kk][tr * 8 + 4];
            *(float4*)&b[0] = *(const float4*)&Bs[kk][tc * 8];
            *(float4*)&b[4] = *(const float4*)&Bs[kk][tc * 8 + 4];
            #pragma unroll
            for (int i = 0; i < 8; i++)
                #pragma unroll
                for (int j = 0; j < 8; j++)
                    acc[i][j] += a[i] * b[j];
        }
        __syncthreads();
    }

    #pragma unroll
    for (int i = 0; i < 8; i++) {
        int r = bm + tr * 8 + i;
        #pragma unroll
        for (int j = 0; j < 8; j += 4) {
            int c = bn + tc * 8 + j;
            float4 v;
            v.x = acc[i][j + 0] + bias[c + 0];
            v.y = acc[i][j + 1] + bias[c + 1];
            v.z = acc[i][j + 2] + bias[c + 2];
            v.w = acc[i][j + 3] + bias[c + 3];
            if (RESID) {
                float4 rv = *(const float4*)&resid[(size_t)r * N + c];
                v.x += rv.x; v.y += rv.y; v.z += rv.z; v.w += rv.w;
            }
            *(float4*)&C[(size_t)r * N + c] = v;
        }
    }
}

// ---------------------------------------------------------------------------
// Flash attention, fp32. One thread per query row; 128 q-rows/block, 64-key
// tiles. Causal mask + relative position bias fused. Online softmax.
// Dynamic smem layout: Ks[64*64] | Vs[64*64] | Ss[128*65] | rpbs[192]
// ---------------------------------------------------------------------------
#define BMQ 128
#define BNK 64
#define ATTN_SMEM_FLOATS (BNK * HD + BNK * HD + BMQ * 65 + 192)

extern __shared__ float s_attn[];

__global__ __launch_bounds__(128)
void attn_kernel(const float* __restrict__ qkv, const float* __restrict__ rpb,
                 float* __restrict__ o_out)
{
    float* Ks   = s_attn;                 // [64][64]
    float* Vs   = Ks + BNK * HD;          // [64][64]
    float* Ss   = Vs + BNK * HD;          // [128][65] padded
    float* rpbs = Ss + BMQ * 65;          // [192]

    const int qt = blockIdx.x;
    const int h  = blockIdx.y;
    const int b  = blockIdx.z;
    const int t  = threadIdx.x;           // 0..127
    const int qbase = qt * BMQ;
    const int i = qbase + t;              // global query row within sequence

    // Load this thread's q row (64 floats) into registers
    float4 q[16];
    {
        const float4* qp = (const float4*)&qkv[((size_t)(b * S + i)) * 3 * D + h * HD];
        #pragma unroll
        for (int x = 0; x < 16; x++) q[x] = qp[x];
    }
    float4 o[16];
    #pragma unroll
    for (int x = 0; x < 16; x++) o[x] = make_float4(0.f, 0.f, 0.f, 0.f);
    float m_i = -1e30f, l_i = 0.f;

    const int nkt = qbase / BNK + 2;      // causal: tiles with kbase <= qbase+64
    for (int kt = 0; kt < nkt; kt++) {
        const int kbase = kt * BNK;

        // Load K and V tiles (64x64 floats each): 1024 float4 per tile
        #pragma unroll
        for (int l = 0; l < 8; l++) {
            int f = t + l * 128;          // 0..1023
            int row = f >> 4;             // 0..63
            int c4  = f & 15;             // float4 column
            const float4* kp = (const float4*)
                &qkv[((size_t)(b * S + kbase + row)) * 3 * D + D + h * HD];
            ((float4*)Ks)[row * 16 + c4] = kp[c4];
            const float4* vp = (const float4*)
                &qkv[((size_t)(b * S + kbase + row)) * 3 * D + 2 * D + h * HD];
            ((float4*)Vs)[row * 16 + c4] = vp[c4];
        }
        // rpb slice for this (qtile,ktile): rel = kbase + j - i + (S-1)
        // smem index = j - t + 127, so rel0 corresponds to index 0:
        const int rel0 = kbase - qbase - 127 + (S - 1);
        for (int x = t; x < 192; x += 128) {
            int rel = rel0 + x;
            rpbs[x] = (rel >= 0 && rel < 2 * S - 1) ? rpb[rel * H + h] : 0.f;
        }
        __syncthreads();

        // ---- scores: s_j = (q . K_j)*scale + bias, masked ----
        float tmax = -1e30f;
        #pragma unroll 2
        for (int j = 0; j < BNK; j++) {
            const float4* kr = (const float4*)&Ks[j * HD];
            float sx = 0.f, sy = 0.f, sz = 0.f, sw = 0.f;
            #pragma unroll
            for (int x = 0; x < 16; x++) {
                float4 kv = kr[x];
                sx += q[x].x * kv.x; sy += q[x].y * kv.y;
                sz += q[x].z * kv.z; sw += q[x].w * kv.w;
            }
            float s = (sx + sy) + (sz + sw);
            s = s * SM_SCALE + rpbs[j - t + 127];
            if (kbase + j > i) s = -1e30f;   // causal mask (masked -> -inf + bias = -inf)
            tmax = fmaxf(tmax, s);
            Ss[t * 65 + j] = s;
        }

        // ---- online softmax rescale ----
        float m_new = fmaxf(m_i, tmax);
        float alpha = __expf(m_i - m_new);
        l_i *= alpha;
        #pragma unroll
        for (int x = 0; x < 16; x++) {
            o[x].x *= alpha; o[x].y *= alpha; o[x].z *= alpha; o[x].w *= alpha;
        }

        // ---- accumulate O += P @ V ----
        #pragma unroll 2
        for (int j = 0; j < BNK; j++) {
            float p = __expf(Ss[t * 65 + j] - m_new);
            l_i += p;
            const float4* vr = (const float4*)&Vs[j * HD];
            #pragma unroll
            for (int x = 0; x < 16; x++) {
                float4 vv = vr[x];
                o[x].x += p * vv.x; o[x].y += p * vv.y;
                o[x].z += p * vv.z; o[x].w += p * vv.w;
            }
        }
        m_i = m_new;
        __syncthreads();   // protect Ks/Vs/rpbs before next tile overwrite
    }

    const float inv = 1.f / l_i;
    float4* op = (float4*)&o_out[((size_t)(b * S + i)) * D + h * HD];
    #pragma unroll
    for (int x = 0; x < 16; x++) {
        float4 v = o[x];
        v.x *= inv; v.y *= inv; v.z *= inv; v.w *= inv;
        op[x] = v;
    }
}

// ---------------------------------------------------------------------------
// LayerNorm: one block per row of y [4096, 1024]
// ---------------------------------------------------------------------------
__global__ __launch_bounds__(256)
void ln_kernel(const float* __restrict__ y, const float* __restrict__ g,
               const float* __restrict__ beta, float* __restrict__ out)
{
    const int row = blockIdx.x;
    const int t = threadIdx.x;            // 0..255, D/4 = 256 float4 per row
    const float4* yp = (const float4*)&y[(size_t)row * D];
    float4 v = yp[t];

    float s  = v.x + v.y + v.z + v.w;
    float ss = v.x * v.x + v.y * v.y + v.z * v.z + v.w * v.w;
    #pragma unroll
    for (int off = 16; off > 0; off >>= 1) {
        s  += __shfl_xor_sync(0xffffffffu, s,  off);
        ss += __shfl_xor_sync(0xffffffffu, ss, off);
    }
    __shared__ float sh[16];
    __shared__ float s_mu, s_rstd;
    const int w = t >> 5, lane = t & 31;
    if (lane == 0) { sh[w] = s; sh[8 + w] = ss; }
    __syncthreads();
    if (t == 0) {
        float S0 = 0.f, S1 = 0.f;
        #pragma unroll
        for (int x = 0; x < 8; x++) { S0 += sh[x]; S1 += sh[8 + x]; }
        float mu = S0 * (1.0f / D);
        float var = S1 * (1.0f / D) - mu * mu;
        s_mu = mu;
        s_rstd = rsqrtf(var + LN_EPS);
    }
    __syncthreads();
    const float mu = s_mu, r = s_rstd;
    float4 gv = ((const float4*)g)[t];
    float4 bv = ((const float4*)beta)[t];
    float4 ov;
    ov.x = (v.x - mu) * r * gv.x + bv.x;
    ov.y = (v.y - mu) * r * gv.y + bv.y;
    ov.z = (v.z - mu) * r * gv.z + bv.z;
    ov.w = (v.w - mu) * r * gv.w + bv.w;
    ((float4*)&out[(size_t)row * D])[t] = ov;
}

// ---------------------------------------------------------------------------
extern "C" void kernel_launch(void* const* d_in, const int* in_sizes, int n_in,
                              void* d_out, int out_size)
{
    const float* x      = (const float*)d_in[0];   // [B,S,D]
    const float* W_w    = (const float*)d_in[1];   // [3D,D]
    const float* W_b    = (const float*)d_in[2];   // [3D]
    const float* proj_w = (const float*)d_in[3];   // [D,D]
    const float* proj_b = (const float*)d_in[4];   // [D]
    const float* ln_g   = (const float*)d_in[5];   // [D]
    const float* ln_b   = (const float*)d_in[6];   // [D]
    const float* rpb    = (const float*)d_in[7];   // [2S-1,H]
    float* out = (float*)d_out;

    float *qkv, *obuf, *ybuf;
    cudaGetSymbolAddress((void**)&qkv,  g_qkv);
    cudaGetSymbolAddress((void**)&obuf, g_o);
    cudaGetSymbolAddress((void**)&ybuf, g_y);

    const int attn_smem = ATTN_SMEM_FLOATS * (int)sizeof(float);   // 66816 B
    cudaFuncSetAttribute(attn_kernel,
                         cudaFuncAttributeMaxDynamicSharedMemorySize, attn_smem);

    // 1) QKV = x @ W_w^T + W_b        [4096, 3072]
    {
        dim3 grid(3 * D / 128, M_ROWS / 128);
        gemm_nt<false><<<grid, 256>>>(x, W_w, W_b, nullptr, qkv,
                                      M_ROWS, 3 * D, D);
    }
    // 2) attention -> obuf [4096, 1024]
    {
        dim3 grid(S / BMQ, H, BATCH);
        attn_kernel<<<grid, 128, attn_smem>>>(qkv, rpb, obuf);
    }
    // 3) y = obuf @ proj_w^T + proj_b + x   [4096, 1024]
    {
        dim3 grid(D / 128, M_ROWS / 128);
        gemm_nt<true><<<grid, 256>>>(obuf, proj_w, proj_b, x, ybuf,
                                     M_ROWS, D, D);
    }
    // 4) out = LayerNorm(y)
    ln_kernel<<<M_ROWS, 256>>>(ybuf, ln_g, ln_b, out);
}

// round 3
// speedup vs baseline: 1.3052x; 1.3052x over previous
#include <cuda_runtime.h>
#include <cuda_bf16.h>
#include <cstdint>
#include <cstddef>

#define D 1024
#define H 16
#define HD 64
#define S 2048
#define BATCH 2
#define M_ROWS (BATCH * S)        // 4096
#define LN_EPS 1e-5f
#define SM_SCALE (1.0f / 32.0f)   // 1/sqrt(D)

// ---------------------------------------------------------------------------
// Scratch (no allocations allowed in kernel_launch)
// ---------------------------------------------------------------------------
__device__ float g_qkv[(size_t)M_ROWS * 3 * D];
__device__ float g_o[(size_t)M_ROWS * D];
__device__ float g_y[(size_t)M_ROWS * D];
__device__ __nv_bfloat16 g_xh[(size_t)M_ROWS * D];
__device__ __nv_bfloat16 g_xl[(size_t)M_ROWS * D];
__device__ __nv_bfloat16 g_wh[(size_t)3 * D * D];
__device__ __nv_bfloat16 g_wl[(size_t)3 * D * D];
__device__ __nv_bfloat16 g_ph[(size_t)D * D];
__device__ __nv_bfloat16 g_pl[(size_t)D * D];
__device__ __nv_bfloat16 g_oh[(size_t)M_ROWS * D];
__device__ __nv_bfloat16 g_ol[(size_t)M_ROWS * D];

// ---------------------------------------------------------------------------
// PTX helpers (sm_100-legal: mma.sync / ldmatrix / cp.async)
// ---------------------------------------------------------------------------
__device__ __forceinline__ uint32_t smem_u32(const void* p) {
    uint32_t a;
    asm("{ .reg .u64 t; cvta.to.shared.u64 t, %1; cvt.u32.u64 %0, t; }"
        : "=r"(a) : "l"(p));
    return a;
}
__device__ __forceinline__ void cp_async16(uint32_t s, const void* g) {
    asm volatile("cp.async.cg.shared.global [%0], [%1], 16;" :: "r"(s), "l"(g));
}
#define CP_COMMIT() asm volatile("cp.async.commit_group;" ::: "memory")
#define CP_WAIT(n)  asm volatile("cp.async.wait_group %0;" :: "n"(n) : "memory")

__device__ __forceinline__ void ldsm4(uint32_t& r0, uint32_t& r1, uint32_t& r2,
                                      uint32_t& r3, uint32_t addr) {
    asm volatile("ldmatrix.sync.aligned.m8n8.x4.shared.b16 {%0,%1,%2,%3}, [%4];"
                 : "=r"(r0), "=r"(r1), "=r"(r2), "=r"(r3) : "r"(addr));
}
__device__ __forceinline__ void mma16816(float* c, const uint32_t* a,
                                         uint32_t b0, uint32_t b1) {
    asm volatile(
        "mma.sync.aligned.m16n8k16.row.col.f32.bf16.bf16.f32 "
        "{%0,%1,%2,%3}, {%4,%5,%6,%7}, {%8,%9}, {%0,%1,%2,%3};"
        : "+f"(c[0]), "+f"(c[1]), "+f"(c[2]), "+f"(c[3])
        : "r"(a[0]), "r"(a[1]), "r"(a[2]), "r"(a[3]), "r"(b0), "r"(b1));
}

// ---------------------------------------------------------------------------
// fp32 -> (bf16 hi, bf16 lo) split
// ---------------------------------------------------------------------------
__global__ __launch_bounds__(256)
void split_kernel(const float* __restrict__ src, __nv_bfloat16* __restrict__ hi,
                  __nv_bfloat16* __restrict__ lo, int n4)
{
    int i = blockIdx.x * blockDim.x + threadIdx.x;
    if (i >= n4) return;
    float4 v = ((const float4*)src)[i];
    __nv_bfloat16 hx = __float2bfloat16(v.x);
    __nv_bfloat16 hy = __float2bfloat16(v.y);
    __nv_bfloat16 hz = __float2bfloat16(v.z);
    __nv_bfloat16 hw = __float2bfloat16(v.w);
    __nv_bfloat162 h0; h0.x = hx; h0.y = hy;
    __nv_bfloat162 h1; h1.x = hz; h1.y = hw;
    __nv_bfloat162 l0, l1;
    l0.x = __float2bfloat16(v.x - __bfloat162float(hx));
    l0.y = __float2bfloat16(v.y - __bfloat162float(hy));
    l1.x = __float2bfloat16(v.z - __bfloat162float(hz));
    l1.y = __float2bfloat16(v.w - __bfloat162float(hw));
    ((__nv_bfloat162*)hi)[2 * i]     = h0;
    ((__nv_bfloat162*)hi)[2 * i + 1] = h1;
    ((__nv_bfloat162*)lo)[2 * i]     = l0;
    ((__nv_bfloat162*)lo)[2 * i + 1] = l1;
}

// ---------------------------------------------------------------------------
// mma.sync bf16x3 GEMM (NT): C[M,N] = A[M,K=1024] @ Bt[N,K]^T + bias (+resid)
// CTA tile 128x128x32, 8 warps (2x4), warp tile 64x32, double-buffered cp.async.
// C = Ah*Bh + Ah*Bl + Al*Bh, fp32 accum.
// ---------------------------------------------------------------------------
#define GK D                       // K = 1024 for both GEMMs
#define BKK 32                     // bf16 k per stage
#define TSTRIDE 80                 // smem row pitch bytes (32 bf16 + 8 pad)
#define TILE_BYTES (128 * TSTRIDE) // 10240
#define STAGE_BYTES (4 * TILE_BYTES)
#define GEMM_SMEM (2 * STAGE_BYTES) // 81920

template <bool RESID>
__global__ __launch_bounds__(256, 1)
void gemm_mma(const __nv_bfloat16* __restrict__ Ah, const __nv_bfloat16* __restrict__ Al,
              const __nv_bfloat16* __restrict__ Bh, const __nv_bfloat16* __restrict__ Bl,
              const float* __restrict__ bias, const float* __restrict__ resid,
              float* __restrict__ C, int N)
{
    extern __shared__ char sm[];
    const uint32_t sbase = smem_u32(sm);

    const int tid  = threadIdx.x;
    const int wid  = tid >> 5;
    const int lane = tid & 31;
    const int bm = blockIdx.y * 128;
    const int bn = blockIdx.x * 128;
    const int wm = wid & 1;          // 0..1
    const int wn = wid >> 1;         // 0..3

    const __nv_bfloat16* tsrc[4] = { Ah, Al, Bh, Bl };

    // chunk loader constants: per tile 512 chunks (128 rows x 4 x 16B)
    const int lrow = tid >> 1;                 // not used; loader below per-chunk

    float acc[4][4][4];
    #pragma unroll
    for (int i = 0; i < 4; i++)
        #pragma unroll
        for (int j = 0; j < 4; j++)
            #pragma unroll
            for (int r = 0; r < 4; r++) acc[i][j][r] = 0.f;

    auto load_stage = [&](int stage, int k0) {
        uint32_t sst = sbase + stage * STAGE_BYTES;
        #pragma unroll
        for (int tile = 0; tile < 4; tile++) {
            const __nv_bfloat16* src = tsrc[tile];
            const int rowbase = (tile < 2) ? bm : bn;
            #pragma unroll
            for (int i = 0; i < 2; i++) {
                int ci  = tid + i * 256;       // 0..511
                int row = ci >> 2;
                int cc  = ci & 3;
                uint32_t sdst = sst + tile * TILE_BYTES + row * TSTRIDE + cc * 16;
                const void* g = (const void*)(src + (size_t)(rowbase + row) * GK + k0 + cc * 8);
                cp_async16(sdst, g);
            }
        }
        CP_COMMIT();
    };

    // ldmatrix per-lane offsets
    const int a_row  = lane & 15;
    const int a_koff = (lane >> 4) << 3;               // 0 or 8 (bf16)
    const int b_row  = (lane & 7) + ((lane & 16) ? 8 : 0);
    const int b_koff = (lane & 8) ? 8 : 0;

    const int NIT = GK / BKK;                           // 32
    load_stage(0, 0);

    for (int it = 0; it < NIT; it++) {
        if (it + 1 < NIT) load_stage((it + 1) & 1, (it + 1) * BKK);
        if (it + 1 < NIT) { CP_WAIT(1); } else { CP_WAIT(0); }
        __syncthreads();

        const uint32_t sst  = sbase + (it & 1) * STAGE_BYTES;
        const uint32_t sAh = sst;
        const uint32_t sAl = sst + TILE_BYTES;
        const uint32_t sBh = sst + 2 * TILE_BYTES;
        const uint32_t sBl = sst + 3 * TILE_BYTES;

        #pragma unroll
        for (int ks = 0; ks < 2; ks++) {
            const int kb = ks * 16;
            uint32_t ah[4][4], al[4][4], bh[2][4], bl[2][4];
            #pragma unroll
            for (int am = 0; am < 4; am++) {
                uint32_t off = (wm * 64 + am * 16 + a_row) * TSTRIDE + (kb + a_koff) * 2;
                ldsm4(ah[am][0], ah[am][1], ah[am][2], ah[am][3], sAh + off);
                ldsm4(al[am][0], al[am][1], al[am][2], al[am][3], sAl + off);
            }
            #pragma unroll
            for (int p = 0; p < 2; p++) {
                uint32_t off = (wn * 32 + p * 16 + b_row) * TSTRIDE + (kb + b_koff) * 2;
                ldsm4(bh[p][0], bh[p][1], bh[p][2], bh[p][3], sBh + off);
                ldsm4(bl[p][0], bl[p][1], bl[p][2], bl[p][3], sBl + off);
            }
            #pragma unroll
            for (int am = 0; am < 4; am++) {
                #pragma unroll
                for (int an = 0; an < 4; an++) {
                    const int p = an >> 1, q = (an & 1) * 2;
                    float* c = acc[am][an];
                    mma16816(c, ah[am], bh[p][q], bh[p][q + 1]);
                    mma16816(c, ah[am], bl[p][q], bl[p][q + 1]);
                    mma16816(c, al[am], bh[p][q], bh[p][q + 1]);
                }
            }
        }
        __syncthreads();
    }

    // Epilogue: c0,c1 -> (row, col..col+1); c2,c3 -> (row+8, ...)
    const int g = lane >> 2, t4 = lane & 3;
    #pragma unroll
    for (int am = 0; am < 4; am++) {
        const int row0 = bm + wm * 64 + am * 16 + g;
        #pragma unroll
        for (int an = 0; an < 4; an++) {
            const int col = bn + wn * 32 + an * 8 + 2 * t4;
            const float* c = acc[am][an];
            const float bx = bias[col], by = bias[col + 1];
            size_t o1 = (size_t)row0 * N + col;
            size_t o2 = (size_t)(row0 + 8) * N + col;
            float2 v1 = make_float2(c[0] + bx, c[1] + by);
            float2 v2 = make_float2(c[2] + bx, c[3] + by);
            if (RESID) {
                float2 r1 = *(const float2*)&resid[o1];
                float2 r2 = *(const float2*)&resid[o2];
                v1.x += r1.x; v1.y += r1.y;
                v2.x += r2.x; v2.y += r2.y;
            }
            *(float2*)&C[o1] = v1;
            *(float2*)&C[o2] = v2;
        }
    }
}

// ---------------------------------------------------------------------------
// Flash attention, fp32 SIMT (proven correct in R0)
// ---------------------------------------------------------------------------
#define BMQ 128
#define BNK 64
#define ATTN_SMEM_FLOATS (BNK * HD + BNK * HD + BMQ * 65 + 192)

extern __shared__ float s_attn[];

__global__ __launch_bounds__(128)
void attn_kernel(const float* __restrict__ qkv, const float* __restrict__ rpb,
                 float* __restrict__ o_out)
{
    float* Ks   = s_attn;
    float* Vs   = Ks + BNK * HD;
    float* Ss   = Vs + BNK * HD;
    float* rpbs = Ss + BMQ * 65;

    const int qt = blockIdx.x;
    const int h  = blockIdx.y;
    const int b  = blockIdx.z;
    const int t  = threadIdx.x;
    const int qbase = qt * BMQ;
    const int i = qbase + t;

    float4 q[16];
    {
        const float4* qp = (const float4*)&qkv[((size_t)(b * S + i)) * 3 * D + h * HD];
        #pragma unroll
        for (int x = 0; x < 16; x++) q[x] = qp[x];
    }
    float4 o[16];
    #pragma unroll
    for (int x = 0; x < 16; x++) o[x] = make_float4(0.f, 0.f, 0.f, 0.f);
    float m_i = -1e30f, l_i = 0.f;

    const int nkt = qbase / BNK + 2;
    for (int kt = 0; kt < nkt; kt++) {
        const int kbase = kt * BNK;
        #pragma unroll
        for (int l = 0; l < 8; l++) {
            int f = t + l * 128;
            int row = f >> 4;
            int c4  = f & 15;
            const float4* kp = (const float4*)
                &qkv[((size_t)(b * S + kbase + row)) * 3 * D + D + h * HD];
            ((float4*)Ks)[row * 16 + c4] = kp[c4];
            const float4* vp = (const float4*)
                &qkv[((size_t)(b * S + kbase + row)) * 3 * D + 2 * D + h * HD];
            ((float4*)Vs)[row * 16 + c4] = vp[c4];
        }
        const int rel0 = kbase - qbase - 127 + (S - 1);
        for (int x = t; x < 192; x += 128) {
            int rel = rel0 + x;
            rpbs[x] = (rel >= 0 && rel < 2 * S - 1) ? rpb[rel * H + h] : 0.f;
        }
        __syncthreads();

        float tmax = -1e30f;
        #pragma unroll 2
        for (int j = 0; j < BNK; j++) {
            const float4* kr = (const float4*)&Ks[j * HD];
            float sx = 0.f, sy = 0.f, sz = 0.f, sw = 0.f;
            #pragma unroll
            for (int x = 0; x < 16; x++) {
                float4 kv = kr[x];
                sx += q[x].x * kv.x; sy += q[x].y * kv.y;
                sz += q[x].z * kv.z; sw += q[x].w * kv.w;
            }
            float s = (sx + sy) + (sz + sw);
            s = s * SM_SCALE + rpbs[j - t + 127];
            if (kbase + j > i) s = -1e30f;
            tmax = fmaxf(tmax, s);
            Ss[t * 65 + j] = s;
        }

        float m_new = fmaxf(m_i, tmax);
        float alpha = __expf(m_i - m_new);
        l_i *= alpha;
        #pragma unroll
        for (int x = 0; x < 16; x++) {
            o[x].x *= alpha; o[x].y *= alpha; o[x].z *= alpha; o[x].w *= alpha;
        }

        #pragma unroll 2
        for (int j = 0; j < BNK; j++) {
            float p = __expf(Ss[t * 65 + j] - m_new);
            l_i += p;
            const float4* vr = (const float4*)&Vs[j * HD];
            #pragma unroll
            for (int x = 0; x < 16; x++) {
                float4 vv = vr[x];
                o[x].x += p * vv.x; o[x].y += p * vv.y;
                o[x].z += p * vv.z; o[x].w += p * vv.w;
            }
        }
        m_i = m_new;
        __syncthreads();
    }

    const float inv = 1.f / l_i;
    float4* op = (float4*)&o_out[((size_t)(b * S + i)) * D + h * HD];
    #pragma unroll
    for (int x = 0; x < 16; x++) {
        float4 v = o[x];
        v.x *= inv; v.y *= inv; v.z *= inv; v.w *= inv;
        op[x] = v;
    }
}

// ---------------------------------------------------------------------------
// LayerNorm: one block per row [4096, 1024]
// ---------------------------------------------------------------------------
__global__ __launch_bounds__(256)
void ln_kernel(const float* __restrict__ y, const float* __restrict__ g,
               const float* __restrict__ beta, float* __restrict__ out)
{
    const int row = blockIdx.x;
    const int t = threadIdx.x;
    const float4* yp = (const float4*)&y[(size_t)row * D];
    float4 v = yp[t];

    float s  = v.x + v.y + v.z + v.w;
    float ss = v.x * v.x + v.y * v.y + v.z * v.z + v.w * v.w;
    #pragma unroll
    for (int off = 16; off > 0; off >>= 1) {
        s  += __shfl_xor_sync(0xffffffffu, s,  off);
        ss += __shfl_xor_sync(0xffffffffu, ss, off);
    }
    __shared__ float sh[16];
    __shared__ float s_mu, s_rstd;
    const int w = t >> 5, lane = t & 31;
    if (lane == 0) { sh[w] = s; sh[8 + w] = ss; }
    __syncthreads();
    if (t == 0) {
        float S0 = 0.f, S1 = 0.f;
        #pragma unroll
        for (int x = 0; x < 8; x++) { S0 += sh[x]; S1 += sh[8 + x]; }
        float mu = S0 * (1.0f / D);
        float var = S1 * (1.0f / D) - mu * mu;
        s_mu = mu;
        s_rstd = rsqrtf(var + LN_EPS);
    }
    __syncthreads();
    const float mu = s_mu, r = s_rstd;
    float4 gv = ((const float4*)g)[t];
    float4 bv = ((const float4*)beta)[t];
    float4 ov;
    ov.x = (v.x - mu) * r * gv.x + bv.x;
    ov.y = (v.y - mu) * r * gv.y + bv.y;
    ov.z = (v.z - mu) * r * gv.z + bv.z;
    ov.w = (v.w - mu) * r * gv.w + bv.w;
    ((float4*)&out[(size_t)row * D])[t] = ov;
}

// ---------------------------------------------------------------------------
extern "C" void kernel_launch(void* const* d_in, const int* in_sizes, int n_in,
                              void* d_out, int out_size)
{
    const float* x      = (const float*)d_in[0];
    const float* W_w    = (const float*)d_in[1];
    const float* W_b    = (const float*)d_in[2];
    const float* proj_w = (const float*)d_in[3];
    const float* proj_b = (const float*)d_in[4];
    const float* ln_g   = (const float*)d_in[5];
    const float* ln_b   = (const float*)d_in[6];
    const float* rpb    = (const float*)d_in[7];
    float* out = (float*)d_out;

    float *qkv, *obuf, *ybuf;
    __nv_bfloat16 *xh, *xl, *wh, *wl, *ph, *pl, *oh, *ol;
    cudaGetSymbolAddress((void**)&qkv,  g_qkv);
    cudaGetSymbolAddress((void**)&obuf, g_o);
    cudaGetSymbolAddress((void**)&ybuf, g_y);
    cudaGetSymbolAddress((void**)&xh, g_xh);
    cudaGetSymbolAddress((void**)&xl, g_xl);
    cudaGetSymbolAddress((void**)&wh, g_wh);
    cudaGetSymbolAddress((void**)&wl, g_wl);
    cudaGetSymbolAddress((void**)&ph, g_ph);
    cudaGetSymbolAddress((void**)&pl, g_pl);
    cudaGetSymbolAddress((void**)&oh, g_oh);
    cudaGetSymbolAddress((void**)&ol, g_ol);

    const int attn_smem = ATTN_SMEM_FLOATS * (int)sizeof(float);
    cudaFuncSetAttribute(attn_kernel,
                         cudaFuncAttributeMaxDynamicSharedMemorySize, attn_smem);
    cudaFuncSetAttribute(gemm_mma<false>,
                         cudaFuncAttributeMaxDynamicSharedMemorySize, GEMM_SMEM);
    cudaFuncSetAttribute(gemm_mma<true>,
                         cudaFuncAttributeMaxDynamicSharedMemorySize, GEMM_SMEM);

    // 0) bf16 hi/lo splits
    split_kernel<<<(M_ROWS * D / 4 + 255) / 256, 256>>>(x, xh, xl, M_ROWS * D / 4);
    split_kernel<<<(3 * D * D / 4 + 255) / 256, 256>>>(W_w, wh, wl, 3 * D * D / 4);
    split_kernel<<<(D * D / 4 + 255) / 256, 256>>>(proj_w, ph, pl, D * D / 4);

    // 1) QKV = x @ W_w^T + W_b   [4096, 3072]
    {
        dim3 grid(3 * D / 128, M_ROWS / 128);
        gemm_mma<false><<<grid, 256, GEMM_SMEM>>>(xh, xl, wh, wl, W_b, nullptr,
                                                  qkv, 3 * D);
    }
    // 2) attention -> obuf
    {
        dim3 grid(S / BMQ, H, BATCH);
        attn_kernel<<<grid, 128, attn_smem>>>(qkv, rpb, obuf);
    }
    // 3) y = o @ proj_w^T + proj_b + x
    split_kernel<<<(M_ROWS * D / 4 + 255) / 256, 256>>>(obuf, oh, ol, M_ROWS * D / 4);
    {
        dim3 grid(D / 128, M_ROWS / 128);
        gemm_mma<true><<<grid, 256, GEMM_SMEM>>>(oh, ol, ph, pl, proj_b, x,
                                                 ybuf, D);
    }
    // 4) LayerNorm
    ln_kernel<<<M_ROWS, 256>>>(ybuf, ln_g, ln_b, out);
}

// round 4
// speedup vs baseline: 3.4122x; 2.6143x over previous
#include <cuda_runtime.h>
#include <cuda_bf16.h>
#include <cstdint>
#include <cstddef>

#define D 1024
#define H 16
#define HD 64
#define S 2048
#define BATCH 2
#define M_ROWS (BATCH * S)        // 4096
#define LN_EPS 1e-5f
#define SM_SCALE (1.0f / 32.0f)   // 1/sqrt(D)

// ---------------------------------------------------------------------------
// Scratch
// ---------------------------------------------------------------------------
__device__ float g_qkv[(size_t)M_ROWS * 3 * D];
__device__ float g_y[(size_t)M_ROWS * D];
__device__ __nv_bfloat16 g_xh[(size_t)M_ROWS * D];
__device__ __nv_bfloat16 g_xl[(size_t)M_ROWS * D];
__device__ __nv_bfloat16 g_wh[(size_t)3 * D * D];
__device__ __nv_bfloat16 g_wl[(size_t)3 * D * D];
__device__ __nv_bfloat16 g_ph[(size_t)D * D];
__device__ __nv_bfloat16 g_pl[(size_t)D * D];
__device__ __nv_bfloat16 g_oh[(size_t)M_ROWS * D];
__device__ __nv_bfloat16 g_ol[(size_t)M_ROWS * D];

// ---------------------------------------------------------------------------
// PTX helpers (sm_100-legal)
// ---------------------------------------------------------------------------
__device__ __forceinline__ uint32_t smem_u32(const void* p) {
    uint32_t a;
    asm("{ .reg .u64 t; cvta.to.shared.u64 t, %1; cvt.u32.u64 %0, t; }"
        : "=r"(a) : "l"(p));
    return a;
}
__device__ __forceinline__ void cp_async16(uint32_t s, const void* g) {
    asm volatile("cp.async.cg.shared.global [%0], [%1], 16;" :: "r"(s), "l"(g));
}
#define CP_COMMIT() asm volatile("cp.async.commit_group;" ::: "memory")
#define CP_WAIT(n)  asm volatile("cp.async.wait_group %0;" :: "n"(n) : "memory")

__device__ __forceinline__ void ldsm4(uint32_t& r0, uint32_t& r1, uint32_t& r2,
                                      uint32_t& r3, uint32_t addr) {
    asm volatile("ldmatrix.sync.aligned.m8n8.x4.shared.b16 {%0,%1,%2,%3}, [%4];"
                 : "=r"(r0), "=r"(r1), "=r"(r2), "=r"(r3) : "r"(addr));
}
__device__ __forceinline__ void ldsm4t(uint32_t& r0, uint32_t& r1, uint32_t& r2,
                                       uint32_t& r3, uint32_t addr) {
    asm volatile("ldmatrix.sync.aligned.m8n8.x4.trans.shared.b16 {%0,%1,%2,%3}, [%4];"
                 : "=r"(r0), "=r"(r1), "=r"(r2), "=r"(r3) : "r"(addr));
}
__device__ __forceinline__ void mma16816(float* c, const uint32_t* a,
                                         uint32_t b0, uint32_t b1) {
    asm volatile(
        "mma.sync.aligned.m16n8k16.row.col.f32.bf16.bf16.f32 "
        "{%0,%1,%2,%3}, {%4,%5,%6,%7}, {%8,%9}, {%0,%1,%2,%3};"
        : "+f"(c[0]), "+f"(c[1]), "+f"(c[2]), "+f"(c[3])
        : "r"(a[0]), "r"(a[1]), "r"(a[2]), "r"(a[3]), "r"(b0), "r"(b1));
}

// Fast exp on the FMA pipe (no MUFU). Rel err ~2e-6, exact 0 handling via clamp.
__device__ __forceinline__ float fexp(float x) {
    x = fmaxf(x, -80.f);
    float t = fmaf(x, 1.4426950408889634f, 12582912.0f);  // round via magic
    float k = t - 12582912.0f;
    float f = fmaf(x, 1.4426950408889634f, -k);           // [-0.5, 0.5]
    float p = 1.3333558146428443e-3f;
    p = fmaf(p, f, 9.6181291076284771e-3f);
    p = fmaf(p, f, 5.5504108664821580e-2f);
    p = fmaf(p, f, 2.4022650695910071e-1f);
    p = fmaf(p, f, 6.9314718055994531e-1f);
    p = fmaf(p, f, 1.0f);
    int ki = __float_as_int(t) - 0x4B400000;
    return __int_as_float((ki + 127) << 23) * p;
}

__device__ __forceinline__ uint32_t pack_bf16(float a, float b) {
    __nv_bfloat162 h = __floats2bfloat162_rn(a, b);
    return *(uint32_t*)&h;
}

// ---------------------------------------------------------------------------
// fp32 -> (bf16 hi, bf16 lo) split
// ---------------------------------------------------------------------------
__global__ __launch_bounds__(256)
void split_kernel(const float* __restrict__ src, __nv_bfloat16* __restrict__ hi,
                  __nv_bfloat16* __restrict__ lo, int n4)
{
    int i = blockIdx.x * blockDim.x + threadIdx.x;
    if (i >= n4) return;
    float4 v = ((const float4*)src)[i];
    __nv_bfloat16 hx = __float2bfloat16(v.x);
    __nv_bfloat16 hy = __float2bfloat16(v.y);
    __nv_bfloat16 hz = __float2bfloat16(v.z);
    __nv_bfloat16 hw = __float2bfloat16(v.w);
    __nv_bfloat162 h0; h0.x = hx; h0.y = hy;
    __nv_bfloat162 h1; h1.x = hz; h1.y = hw;
    __nv_bfloat162 l0, l1;
    l0.x = __float2bfloat16(v.x - __bfloat162float(hx));
    l0.y = __float2bfloat16(v.y - __bfloat162float(hy));
    l1.x = __float2bfloat16(v.z - __bfloat162float(hz));
    l1.y = __float2bfloat16(v.w - __bfloat162float(hw));
    ((__nv_bfloat162*)hi)[2 * i]     = h0;
    ((__nv_bfloat162*)hi)[2 * i + 1] = h1;
    ((__nv_bfloat162*)lo)[2 * i]     = l0;
    ((__nv_bfloat162*)lo)[2 * i + 1] = l1;
}

// ---------------------------------------------------------------------------
// mma.sync bf16x3 GEMM (NT) — unchanged from R2 (passing, 46.8% tensor)
// ---------------------------------------------------------------------------
#define GK D
#define BKK 32
#define TSTRIDE 80
#define TILE_BYTES (128 * TSTRIDE)
#define STAGE_BYTES (4 * TILE_BYTES)
#define GEMM_SMEM (2 * STAGE_BYTES)

template <bool RESID>
__global__ __launch_bounds__(256, 1)
void gemm_mma(const __nv_bfloat16* __restrict__ Ah, const __nv_bfloat16* __restrict__ Al,
              const __nv_bfloat16* __restrict__ Bh, const __nv_bfloat16* __restrict__ Bl,
              const float* __restrict__ bias, const float* __restrict__ resid,
              float* __restrict__ C, int N)
{
    extern __shared__ char sm[];
    const uint32_t sbase = smem_u32(sm);

    const int tid  = threadIdx.x;
    const int wid  = tid >> 5;
    const int lane = tid & 31;
    const int bm = blockIdx.y * 128;
    const int bn = blockIdx.x * 128;
    const int wm = wid & 1;
    const int wn = wid >> 1;

    const __nv_bfloat16* tsrc[4] = { Ah, Al, Bh, Bl };

    float acc[4][4][4];
    #pragma unroll
    for (int i = 0; i < 4; i++)
        #pragma unroll
        for (int j = 0; j < 4; j++)
            #pragma unroll
            for (int r = 0; r < 4; r++) acc[i][j][r] = 0.f;

    auto load_stage = [&](int stage, int k0) {
        uint32_t sst = sbase + stage * STAGE_BYTES;
        #pragma unroll
        for (int tile = 0; tile < 4; tile++) {
            const __nv_bfloat16* src = tsrc[tile];
            const int rowbase = (tile < 2) ? bm : bn;
            #pragma unroll
            for (int i = 0; i < 2; i++) {
                int ci  = tid + i * 256;
                int row = ci >> 2;
                int cc  = ci & 3;
                uint32_t sdst = sst + tile * TILE_BYTES + row * TSTRIDE + cc * 16;
                const void* g = (const void*)(src + (size_t)(rowbase + row) * GK + k0 + cc * 8);
                cp_async16(sdst, g);
            }
        }
        CP_COMMIT();
    };

    const int a_row  = lane & 15;
    const int a_koff = (lane >> 4) << 3;
    const int b_row  = (lane & 7) + ((lane & 16) ? 8 : 0);
    const int b_koff = (lane & 8) ? 8 : 0;

    const int NIT = GK / BKK;
    load_stage(0, 0);

    for (int it = 0; it < NIT; it++) {
        if (it + 1 < NIT) load_stage((it + 1) & 1, (it + 1) * BKK);
        if (it + 1 < NIT) { CP_WAIT(1); } else { CP_WAIT(0); }
        __syncthreads();

        const uint32_t sst  = sbase + (it & 1) * STAGE_BYTES;
        const uint32_t sAh = sst;
        const uint32_t sAl = sst + TILE_BYTES;
        const uint32_t sBh = sst + 2 * TILE_BYTES;
        const uint32_t sBl = sst + 3 * TILE_BYTES;

        #pragma unroll
        for (int ks = 0; ks < 2; ks++) {
            const int kb = ks * 16;
            uint32_t ah[4][4], al[4][4], bh[2][4], bl[2][4];
            #pragma unroll
            for (int am = 0; am < 4; am++) {
                uint32_t off = (wm * 64 + am * 16 + a_row) * TSTRIDE + (kb + a_koff) * 2;
                ldsm4(ah[am][0], ah[am][1], ah[am][2], ah[am][3], sAh + off);
                ldsm4(al[am][0], al[am][1], al[am][2], al[am][3], sAl + off);
            }
            #pragma unroll
            for (int p = 0; p < 2; p++) {
                uint32_t off = (wn * 32 + p * 16 + b_row) * TSTRIDE + (kb + b_koff) * 2;
                ldsm4(bh[p][0], bh[p][1], bh[p][2], bh[p][3], sBh + off);
                ldsm4(bl[p][0], bl[p][1], bl[p][2], bl[p][3], sBl + off);
            }
            #pragma unroll
            for (int am = 0; am < 4; am++) {
                #pragma unroll
                for (int an = 0; an < 4; an++) {
                    const int p = an >> 1, q = (an & 1) * 2;
                    float* c = acc[am][an];
                    mma16816(c, ah[am], bh[p][q], bh[p][q + 1]);
                    mma16816(c, ah[am], bl[p][q], bl[p][q + 1]);
                    mma16816(c, al[am], bh[p][q], bh[p][q + 1]);
                }
            }
        }
        __syncthreads();
    }

    const int g = lane >> 2, t4 = lane & 3;
    #pragma unroll
    for (int am = 0; am < 4; am++) {
        const int row0 = bm + wm * 64 + am * 16 + g;
        #pragma unroll
        for (int an = 0; an < 4; an++) {
            const int col = bn + wn * 32 + an * 8 + 2 * t4;
            const float* c = acc[am][an];
            const float bx = bias[col], by = bias[col + 1];
            size_t o1 = (size_t)row0 * N + col;
            size_t o2 = (size_t)(row0 + 8) * N + col;
            float2 v1 = make_float2(c[0] + bx, c[1] + by);
            float2 v2 = make_float2(c[2] + bx, c[3] + by);
            if (RESID) {
                float2 r1 = *(const float2*)&resid[o1];
                float2 r2 = *(const float2*)&resid[o2];
                v1.x += r1.x; v1.y += r1.y;
                v2.x += r2.x; v2.y += r2.y;
            }
            *(float2*)&C[o1] = v1;
            *(float2*)&C[o2] = v2;
        }
    }
}

// ---------------------------------------------------------------------------
// Flash attention on mma.sync.
// CTA: 128 q-rows x (head,batch). 8 warps; warp w owns q rows [w*16, w*16+16).
// K-tiles of 64 keys. QK^T bf16 single; P*V bf16x3. fp32 softmax in registers.
// Writes O directly as bf16 hi/lo split for the proj GEMM.
// ---------------------------------------------------------------------------
#define KPITCH 144                       // 64 bf16 = 128B + 16B pad
#define AQ_BYTES (128 * KPITCH)          // Q tile
#define AK_BYTES (64 * KPITCH)           // K / Vh / Vl tiles
#define ATTN_SMEM (AQ_BYTES + 3 * AK_BYTES + 192 * 4)

__global__ __launch_bounds__(256)
void attn_mma(const float* __restrict__ qkv, const float* __restrict__ rpb,
              __nv_bfloat16* __restrict__ OH, __nv_bfloat16* __restrict__ OL)
{
    extern __shared__ char asmem[];
    const uint32_t sQ  = smem_u32(asmem);
    const uint32_t sK  = sQ + AQ_BYTES;
    const uint32_t sVh = sK + AK_BYTES;
    const uint32_t sVl = sVh + AK_BYTES;
    float* rpbs = (float*)(asmem + AQ_BYTES + 3 * AK_BYTES);

    const int qt = gridDim.x - 1 - blockIdx.x;   // heavy tiles first
    const int h  = blockIdx.y;
    const int b  = blockIdx.z;
    const int tid  = threadIdx.x;
    const int wid  = tid >> 5;
    const int lane = tid & 31;
    const int g  = lane >> 2;
    const int t4 = lane & 3;
    const int qbase = qt * 128;

    // ---- load Q tile (fp32 -> bf16) ----
    #pragma unroll
    for (int l = 0; l < 8; l++) {
        int idx = tid + l * 256;          // 0..2047 float4
        int row = idx >> 4;
        int c4  = idx & 15;
        float4 v = *(const float4*)&qkv[((size_t)(b * S + qbase + row)) * 3 * D + h * HD + c4 * 4];
        uint32_t p0 = pack_bf16(v.x, v.y);
        uint32_t p1 = pack_bf16(v.z, v.w);
        *(uint2*)(asmem + (sQ - smem_u32(asmem)) + row * KPITCH + c4 * 8) = make_uint2(p0, p1);
    }
    __syncthreads();

    // ---- preload Q fragments (reused across all k-tiles) ----
    const int a_row  = lane & 15;
    const int a_koff = (lane >> 4) << 3;
    uint32_t qf[4][4];
    #pragma unroll
    for (int kc = 0; kc < 4; kc++) {
        uint32_t off = (wid * 16 + a_row) * KPITCH + (kc * 16 + a_koff) * 2;
        ldsm4(qf[kc][0], qf[kc][1], qf[kc][2], qf[kc][3], sQ + off);
    }

    float o_acc[8][4];
    #pragma unroll
    for (int i = 0; i < 8; i++)
        #pragma unroll
        for (int j = 0; j < 4; j++) o_acc[i][j] = 0.f;
    float mrow[2] = { -1e30f, -1e30f };
    float lrow[2] = { 0.f, 0.f };

    const int b_row  = (lane & 7) + ((lane & 16) ? 8 : 0);
    const int b_koff = (lane & 8) ? 8 : 0;
    const int li0 = wid * 16 + g;                 // local q row (and +8)

    const int nkt = 2 * qt + 2;
    for (int kt = 0; kt < nkt; kt++) {
        const int kbase = kt * 64;
        if (kt) __syncthreads();                  // smem reuse barrier

        // ---- load K (bf16) and V (bf16 hi/lo) tiles ----
        #pragma unroll
        for (int l = 0; l < 4; l++) {
            int idx = tid + l * 256;              // 0..1023
            int row = idx >> 4;
            int c4  = idx & 15;
            size_t base = ((size_t)(b * S + kbase + row)) * 3 * D + h * HD + c4 * 4;
            float4 kv = *(const float4*)&qkv[base + D];
            uint32_t kp0 = pack_bf16(kv.x, kv.y);
            uint32_t kp1 = pack_bf16(kv.z, kv.w);
            *(uint2*)(asmem + (sK - sQ) + row * KPITCH + c4 * 8) = make_uint2(kp0, kp1);
            float4 vv = *(const float4*)&qkv[base + 2 * D];
            __nv_bfloat16 hx = __float2bfloat16(vv.x), hy = __float2bfloat16(vv.y);
            __nv_bfloat16 hz = __float2bfloat16(vv.z), hw = __float2bfloat16(vv.w);
            uint32_t vh0 = pack_bf16(__bfloat162float(hx), __bfloat162float(hy));
            uint32_t vh1 = pack_bf16(__bfloat162float(hz), __bfloat162float(hw));
            uint32_t vl0 = pack_bf16(vv.x - __bfloat162float(hx), vv.y - __bfloat162float(hy));
            uint32_t vl1 = pack_bf16(vv.z - __bfloat162float(hz), vv.w - __bfloat162float(hw));
            *(uint2*)(asmem + (sVh - sQ) + row * KPITCH + c4 * 8) = make_uint2(vh0, vh1);
            *(uint2*)(asmem + (sVl - sQ) + row * KPITCH + c4 * 8) = make_uint2(vl0, vl1);
        }
        if (tid < 192) {
            int ridx = (kbase - qbase - 127) + tid + (S - 1);   // j - i + S-1
            rpbs[tid] = (ridx >= 0 && ridx <= 2 * S - 2) ? rpb[ridx * H + h] : 0.f;
        }
        __syncthreads();

        // ---- scores: S = Q K^T ----
        float sc[8][4];
        #pragma unroll
        for (int i = 0; i < 8; i++)
            #pragma unroll
            for (int j = 0; j < 4; j++) sc[i][j] = 0.f;
        #pragma unroll
        for (int kc = 0; kc < 4; kc++) {
            #pragma unroll
            for (int nb = 0; nb < 4; nb++) {
                uint32_t k0, k1, k2, k3;
                ldsm4(k0, k1, k2, k3,
                      sK + (nb * 16 + b_row) * KPITCH + (kc * 16 + b_koff) * 2);
                mma16816(sc[nb * 2],     qf[kc], k0, k1);
                mma16816(sc[nb * 2 + 1], qf[kc], k2, k3);
            }
        }

        // ---- fixup: scale + rpb + causal mask; row max ----
        float tmax0 = -1e30f, tmax1 = -1e30f;
        #pragma unroll
        for (int blk = 0; blk < 8; blk++) {
            int lj = blk * 8 + 2 * t4;
            int d00 = lj - li0 + 127;              // rpbs index (row g, col lj)
            bool in0 = (kbase + lj)     <= (qbase + li0);
            bool in1 = (kbase + lj + 1) <= (qbase + li0);
            bool in2 = (kbase + lj)     <= (qbase + li0 + 8);
            bool in3 = (kbase + lj + 1) <= (qbase + li0 + 8);
            float v0 = fmaf(sc[blk][0], SM_SCALE, rpbs[d00]);
            float v1 = fmaf(sc[blk][1], SM_SCALE, rpbs[d00 + 1]);
            float v2 = fmaf(sc[blk][2], SM_SCALE, rpbs[d00 - 8]);
            float v3 = fmaf(sc[blk][3], SM_SCALE, rpbs[d00 - 7]);
            v0 = in0 ? v0 : -1e30f;
            v1 = in1 ? v1 : -1e30f;
            v2 = in2 ? v2 : -1e30f;
            v3 = in3 ? v3 : -1e30f;
            sc[blk][0] = v0; sc[blk][1] = v1; sc[blk][2] = v2; sc[blk][3] = v3;
            tmax0 = fmaxf(tmax0, fmaxf(v0, v1));
            tmax1 = fmaxf(tmax1, fmaxf(v2, v3));
        }
        tmax0 = fmaxf(tmax0, __shfl_xor_sync(0xffffffffu, tmax0, 1));
        tmax0 = fmaxf(tmax0, __shfl_xor_sync(0xffffffffu, tmax0, 2));
        tmax1 = fmaxf(tmax1, __shfl_xor_sync(0xffffffffu, tmax1, 1));
        tmax1 = fmaxf(tmax1, __shfl_xor_sync(0xffffffffu, tmax1, 2));

        float mn0 = fmaxf(mrow[0], tmax0);
        float mn1 = fmaxf(mrow[1], tmax1);
        float alpha0 = fexp(mrow[0] - mn0);
        float alpha1 = fexp(mrow[1] - mn1);
        mrow[0] = mn0; mrow[1] = mn1;

        // ---- p = exp(s - m); pack hi/lo A-fragments; row sums ----
        float rs0 = 0.f, rs1 = 0.f;
        uint32_t phf[8][2], plf[8][2];
        #pragma unroll
        for (int blk = 0; blk < 8; blk++) {
            float p0 = fexp(sc[blk][0] - mn0);
            float p1 = fexp(sc[blk][1] - mn0);
            float p2 = fexp(sc[blk][2] - mn1);
            float p3 = fexp(sc[blk][3] - mn1);
            rs0 += p0 + p1;
            rs1 += p2 + p3;
            __nv_bfloat16 h0 = __float2bfloat16(p0), h1 = __float2bfloat16(p1);
            __nv_bfloat16 h2 = __float2bfloat16(p2), h3 = __float2bfloat16(p3);
            phf[blk][0] = pack_bf16(__bfloat162float(h0), __bfloat162float(h1));
            phf[blk][1] = pack_bf16(__bfloat162float(h2), __bfloat162float(h3));
            plf[blk][0] = pack_bf16(p0 - __bfloat162float(h0), p1 - __bfloat162float(h1));
            plf[blk][1] = pack_bf16(p2 - __bfloat162float(h2), p3 - __bfloat162float(h3));
        }
        rs0 += __shfl_xor_sync(0xffffffffu, rs0, 1);
        rs0 += __shfl_xor_sync(0xffffffffu, rs0, 2);
        rs1 += __shfl_xor_sync(0xffffffffu, rs1, 1);
        rs1 += __shfl_xor_sync(0xffffffffu, rs1, 2);
        lrow[0] = lrow[0] * alpha0 + rs0;
        lrow[1] = lrow[1] * alpha1 + rs1;

        // rescale o accumulators
        #pragma unroll
        for (int blk = 0; blk < 8; blk++) {
            o_acc[blk][0] *= alpha0; o_acc[blk][1] *= alpha0;
            o_acc[blk][2] *= alpha1; o_acc[blk][3] *= alpha1;
        }

        // ---- O += P V  (ph*vh + ph*vl + pl*vh) ----
        const int tq = lane >> 3;
        #pragma unroll
        for (int kc = 0; kc < 4; kc++) {
            uint32_t aH[4] = { phf[2 * kc][0], phf[2 * kc][1],
                               phf[2 * kc + 1][0], phf[2 * kc + 1][1] };
            uint32_t aL[4] = { plf[2 * kc][0], plf[2 * kc][1],
                               plf[2 * kc + 1][0], plf[2 * kc + 1][1] };
            #pragma unroll
            for (int nb = 0; nb < 4; nb++) {
                uint32_t roff = (kc * 16 + (tq & 1) * 8 + (lane & 7)) * KPITCH
                              + (nb * 16 + (tq >> 1) * 8) * 2;
                uint32_t vh0, vh1, vh2, vh3, vl0, vl1, vl2, vl3;
                ldsm4t(vh0, vh1, vh2, vh3, sVh + roff);
                ldsm4t(vl0, vl1, vl2, vl3, sVl + roff);
                mma16816(o_acc[nb * 2],     aH, vh0, vh1);
                mma16816(o_acc[nb * 2 + 1], aH, vh2, vh3);
                mma16816(o_acc[nb * 2],     aH, vl0, vl1);
                mma16816(o_acc[nb * 2 + 1], aH, vl2, vl3);
                mma16816(o_acc[nb * 2],     aL, vh0, vh1);
                mma16816(o_acc[nb * 2 + 1], aL, vh2, vh3);
            }
        }
    }

    // ---- epilogue: normalize, split hi/lo, store ----
    const float inv0 = 1.f / lrow[0];
    const float inv1 = 1.f / lrow[1];
    const size_t r0 = (size_t)(b * S + qbase + wid * 16 + g) * D + h * HD;
    const size_t r1 = r0 + 8 * D;
    #pragma unroll
    for (int blk = 0; blk < 8; blk++) {
        int col = blk * 8 + 2 * t4;
        float a0 = o_acc[blk][0] * inv0, a1 = o_acc[blk][1] * inv0;
        float a2 = o_acc[blk][2] * inv1, a3 = o_acc[blk][3] * inv1;
        __nv_bfloat16 h0 = __float2bfloat16(a0), h1 = __float2bfloat16(a1);
        __nv_bfloat16 h2 = __float2bfloat16(a2), h3 = __float2bfloat16(a3);
        __nv_bfloat162 hh0; hh0.x = h0; hh0.y = h1;
        __nv_bfloat162 hh1; hh1.x = h2; hh1.y = h3;
        __nv_bfloat162 ll0 = __floats2bfloat162_rn(a0 - __bfloat162float(h0),
                                                   a1 - __bfloat162float(h1));
        __nv_bfloat162 ll1 = __floats2bfloat162_rn(a2 - __bfloat162float(h2),
                                                   a3 - __bfloat162float(h3));
        *(__nv_bfloat162*)&OH[r0 + col] = hh0;
        *(__nv_bfloat162*)&OL[r0 + col] = ll0;
        *(__nv_bfloat162*)&OH[r1 + col] = hh1;
        *(__nv_bfloat162*)&OL[r1 + col] = ll1;
    }
}

// ---------------------------------------------------------------------------
// LayerNorm
// ---------------------------------------------------------------------------
__global__ __launch_bounds__(256)
void ln_kernel(const float* __restrict__ y, const float* __restrict__ g,
               const float* __restrict__ beta, float* __restrict__ out)
{
    const int row = blockIdx.x;
    const int t = threadIdx.x;
    const float4* yp = (const float4*)&y[(size_t)row * D];
    float4 v = yp[t];

    float s  = v.x + v.y + v.z + v.w;
    float ss = v.x * v.x + v.y * v.y + v.z * v.z + v.w * v.w;
    #pragma unroll
    for (int off = 16; off > 0; off >>= 1) {
        s  += __shfl_xor_sync(0xffffffffu, s,  off);
        ss += __shfl_xor_sync(0xffffffffu, ss, off);
    }
    __shared__ float sh[16];
    __shared__ float s_mu, s_rstd;
    const int w = t >> 5, lane = t & 31;
    if (lane == 0) { sh[w] = s; sh[8 + w] = ss; }
    __syncthreads();
    if (t == 0) {
        float S0 = 0.f, S1 = 0.f;
        #pragma unroll
        for (int x = 0; x < 8; x++) { S0 += sh[x]; S1 += sh[8 + x]; }
        float mu = S0 * (1.0f / D);
        float var = S1 * (1.0f / D) - mu * mu;
        s_mu = mu;
        s_rstd = rsqrtf(var + LN_EPS);
    }
    __syncthreads();
    const float mu = s_mu, r = s_rstd;
    float4 gv = ((const float4*)g)[t];
    float4 bv = ((const float4*)beta)[t];
    float4 ov;
    ov.x = (v.x - mu) * r * gv.x + bv.x;
    ov.y = (v.y - mu) * r * gv.y + bv.y;
    ov.z = (v.z - mu) * r * gv.z + bv.z;
    ov.w = (v.w - mu) * r * gv.w + bv.w;
    ((float4*)&out[(size_t)row * D])[t] = ov;
}

// ---------------------------------------------------------------------------
extern "C" void kernel_launch(void* const* d_in, const int* in_sizes, int n_in,
                              void* d_out, int out_size)
{
    const float* x      = (const float*)d_in[0];
    const float* W_w    = (const float*)d_in[1];
    const float* W_b    = (const float*)d_in[2];
    const float* proj_w = (const float*)d_in[3];
    const float* proj_b = (const float*)d_in[4];
    const float* ln_g   = (const float*)d_in[5];
    const float* ln_b   = (const float*)d_in[6];
    const float* rpb    = (const float*)d_in[7];
    float* out = (float*)d_out;

    float *qkv, *ybuf;
    __nv_bfloat16 *xh, *xl, *wh, *wl, *ph, *pl, *oh, *ol;
    cudaGetSymbolAddress((void**)&qkv,  g_qkv);
    cudaGetSymbolAddress((void**)&ybuf, g_y);
    cudaGetSymbolAddress((void**)&xh, g_xh);
    cudaGetSymbolAddress((void**)&xl, g_xl);
    cudaGetSymbolAddress((void**)&wh, g_wh);
    cudaGetSymbolAddress((void**)&wl, g_wl);
    cudaGetSymbolAddress((void**)&ph, g_ph);
    cudaGetSymbolAddress((void**)&pl, g_pl);
    cudaGetSymbolAddress((void**)&oh, g_oh);
    cudaGetSymbolAddress((void**)&ol, g_ol);

    cudaFuncSetAttribute(gemm_mma<false>,
                         cudaFuncAttributeMaxDynamicSharedMemorySize, GEMM_SMEM);
    cudaFuncSetAttribute(gemm_mma<true>,
                         cudaFuncAttributeMaxDynamicSharedMemorySize, GEMM_SMEM);
    cudaFuncSetAttribute(attn_mma,
                         cudaFuncAttributeMaxDynamicSharedMemorySize, ATTN_SMEM);

    // 0) bf16 hi/lo splits of inputs/weights
    split_kernel<<<(M_ROWS * D / 4 + 255) / 256, 256>>>(x, xh, xl, M_ROWS * D / 4);
    split_kernel<<<(3 * D * D / 4 + 255) / 256, 256>>>(W_w, wh, wl, 3 * D * D / 4);
    split_kernel<<<(D * D / 4 + 255) / 256, 256>>>(proj_w, ph, pl, D * D / 4);

    // 1) QKV = x @ W_w^T + W_b
    {
        dim3 grid(3 * D / 128, M_ROWS / 128);
        gemm_mma<false><<<grid, 256, GEMM_SMEM>>>(xh, xl, wh, wl, W_b, nullptr,
                                                  qkv, 3 * D);
    }
    // 2) attention -> (oh, ol) bf16 split directly
    {
        dim3 grid(S / 128, H, BATCH);
        attn_mma<<<grid, 256, ATTN_SMEM>>>(qkv, rpb, oh, ol);
    }
    // 3) y = o @ proj_w^T + proj_b + x
    {
        dim3 grid(D / 128, M_ROWS / 128);
        gemm_mma<true><<<grid, 256, GEMM_SMEM>>>(oh, ol, ph, pl, proj_b, x,
                                                 ybuf, D);
    }
    // 4) LayerNorm
    ln_kernel<<<M_ROWS, 256>>>(ybuf, ln_g, ln_b, out);
}

// round 7
// speedup vs baseline: 3.8602x; 1.1313x over previous
#include <cuda_runtime.h>
#include <cuda_bf16.h>
#include <cuda_fp16.h>
#include <cstdint>
#include <cstddef>

#define D 1024
#define H 16
#define HD 64
#define S 2048
#define BATCH 2
#define M_ROWS (BATCH * S)        // 4096
#define LN_EPS 1e-5f
#define SM_SCALE (1.0f / 32.0f)   // 1/sqrt(D)

// ---------------------------------------------------------------------------
// Scratch
// ---------------------------------------------------------------------------
__device__ __half g_qkv[(size_t)M_ROWS * 3 * D];      // fp16 qkv (25 MB)
__device__ float g_y[(size_t)M_ROWS * D];
__device__ __nv_bfloat16 g_xh[(size_t)M_ROWS * D];
__device__ __nv_bfloat16 g_xl[(size_t)M_ROWS * D];
__device__ __nv_bfloat16 g_wh[(size_t)3 * D * D];
__device__ __nv_bfloat16 g_wl[(size_t)3 * D * D];
__device__ __nv_bfloat16 g_ph[(size_t)D * D];
__device__ __nv_bfloat16 g_pl[(size_t)D * D];
__device__ __nv_bfloat16 g_oh[(size_t)M_ROWS * D];
__device__ __nv_bfloat16 g_ol[(size_t)M_ROWS * D];

// ---------------------------------------------------------------------------
// PTX helpers (sm_100-legal)
// ---------------------------------------------------------------------------
__device__ __forceinline__ uint32_t smem_u32(const void* p) {
    uint32_t a;
    asm("{ .reg .u64 t; cvta.to.shared.u64 t, %1; cvt.u32.u64 %0, t; }"
        : "=r"(a) : "l"(p));
    return a;
}
__device__ __forceinline__ void cp_async16(uint32_t s, const void* g) {
    asm volatile("cp.async.cg.shared.global [%0], [%1], 16;" :: "r"(s), "l"(g));
}
#define CP_COMMIT() asm volatile("cp.async.commit_group;" ::: "memory")
#define CP_WAIT(n)  asm volatile("cp.async.wait_group %0;" :: "n"(n) : "memory")

__device__ __forceinline__ void ldsm4(uint32_t& r0, uint32_t& r1, uint32_t& r2,
                                      uint32_t& r3, uint32_t addr) {
    asm volatile("ldmatrix.sync.aligned.m8n8.x4.shared.b16 {%0,%1,%2,%3}, [%4];"
                 : "=r"(r0), "=r"(r1), "=r"(r2), "=r"(r3) : "r"(addr));
}
__device__ __forceinline__ void ldsm4t(uint32_t& r0, uint32_t& r1, uint32_t& r2,
                                       uint32_t& r3, uint32_t addr) {
    asm volatile("ldmatrix.sync.aligned.m8n8.x4.trans.shared.b16 {%0,%1,%2,%3}, [%4];"
                 : "=r"(r0), "=r"(r1), "=r"(r2), "=r"(r3) : "r"(addr));
}
__device__ __forceinline__ void mma16816(float* c, const uint32_t* a,
                                         uint32_t b0, uint32_t b1) {
    asm volatile(
        "mma.sync.aligned.m16n8k16.row.col.f32.bf16.bf16.f32 "
        "{%0,%1,%2,%3}, {%4,%5,%6,%7}, {%8,%9}, {%0,%1,%2,%3};"
        : "+f"(c[0]), "+f"(c[1]), "+f"(c[2]), "+f"(c[3])
        : "r"(a[0]), "r"(a[1]), "r"(a[2]), "r"(a[3]), "r"(b0), "r"(b1));
}
__device__ __forceinline__ void mma16816h(float* c, const uint32_t* a,
                                          uint32_t b0, uint32_t b1) {
    asm volatile(
        "mma.sync.aligned.m16n8k16.row.col.f32.f16.f16.f32 "
        "{%0,%1,%2,%3}, {%4,%5,%6,%7}, {%8,%9}, {%0,%1,%2,%3};"
        : "+f"(c[0]), "+f"(c[1]), "+f"(c[2]), "+f"(c[3])
        : "r"(a[0]), "r"(a[1]), "r"(a[2]), "r"(a[3]), "r"(b0), "r"(b1));
}

// Fast exp on the FMA pipe (no MUFU). Rel err ~2e-6.
__device__ __forceinline__ float fexp(float x) {
    x = fmaxf(x, -80.f);
    float t = fmaf(x, 1.4426950408889634f, 12582912.0f);
    float f = fmaf(x, 1.4426950408889634f, -(t - 12582912.0f));
    float p = 1.3333558146428443e-3f;
    p = fmaf(p, f, 9.6181291076284771e-3f);
    p = fmaf(p, f, 5.5504108664821580e-2f);
    p = fmaf(p, f, 2.4022650695910071e-1f);
    p = fmaf(p, f, 6.9314718055994531e-1f);
    p = fmaf(p, f, 1.0f);
    int ki = __float_as_int(t) - 0x4B400000;
    return __int_as_float((ki + 127) << 23) * p;
}

__device__ __forceinline__ uint32_t pack_h2(float a, float b) {
    __half2 h = __floats2half2_rn(a, b);
    return *(uint32_t*)&h;
}

// ---------------------------------------------------------------------------
// fp32 -> (bf16 hi, bf16 lo) split
// ---------------------------------------------------------------------------
__global__ __launch_bounds__(256)
void split_kernel(const float* __restrict__ src, __nv_bfloat16* __restrict__ hi,
                  __nv_bfloat16* __restrict__ lo, int n4)
{
    int i = blockIdx.x * blockDim.x + threadIdx.x;
    if (i >= n4) return;
    float4 v = ((const float4*)src)[i];
    __nv_bfloat16 hx = __float2bfloat16(v.x);
    __nv_bfloat16 hy = __float2bfloat16(v.y);
    __nv_bfloat16 hz = __float2bfloat16(v.z);
    __nv_bfloat16 hw = __float2bfloat16(v.w);
    __nv_bfloat162 h0; h0.x = hx; h0.y = hy;
    __nv_bfloat162 h1; h1.x = hz; h1.y = hw;
    __nv_bfloat162 l0, l1;
    l0.x = __float2bfloat16(v.x - __bfloat162float(hx));
    l0.y = __float2bfloat16(v.y - __bfloat162float(hy));
    l1.x = __float2bfloat16(v.z - __bfloat162float(hz));
    l1.y = __float2bfloat16(v.w - __bfloat162float(hw));
    ((__nv_bfloat162*)hi)[2 * i]     = h0;
    ((__nv_bfloat162*)hi)[2 * i + 1] = h1;
    ((__nv_bfloat162*)lo)[2 * i]     = l0;
    ((__nv_bfloat162*)lo)[2 * i + 1] = l1;
}

// ---------------------------------------------------------------------------
// mma.sync bf16x3 GEMM (NT): 3-stage cp.async pipeline, one barrier per iter.
// C = Ah*Bh + Ah*Bl + Al*Bh, fp32 accum. Output fp32 (+resid) or fp16.
// ---------------------------------------------------------------------------
#define GK D
#define BKK 32
#define TSTRIDE 80
#define TILE_BYTES (128 * TSTRIDE)
#define STAGE_BYTES (4 * TILE_BYTES)      // 40960
#define NSTAGE 3
#define GEMM_SMEM (NSTAGE * STAGE_BYTES)  // 122880

template <bool RESID, bool HOUT>
__global__ __launch_bounds__(256, 1)
void gemm_mma(const __nv_bfloat16* __restrict__ Ah, const __nv_bfloat16* __restrict__ Al,
              const __nv_bfloat16* __restrict__ Bh, const __nv_bfloat16* __restrict__ Bl,
              const float* __restrict__ bias, const float* __restrict__ resid,
              void* __restrict__ Cv, int N)
{
    extern __shared__ char sm[];
    const uint32_t sbase = smem_u32(sm);

    const int tid  = threadIdx.x;
    const int wid  = tid >> 5;
    const int lane = tid & 31;
    const int bm = blockIdx.y * 128;
    const int bn = blockIdx.x * 128;
    const int wm = wid & 1;
    const int wn = wid >> 1;

    const __nv_bfloat16* tsrc[4] = { Ah, Al, Bh, Bl };

    float acc[4][4][4];
    #pragma unroll
    for (int i = 0; i < 4; i++)
        #pragma unroll
        for (int j = 0; j < 4; j++)
            #pragma unroll
            for (int r = 0; r < 4; r++) acc[i][j][r] = 0.f;

    auto load_stage = [&](int stage, int k0) {
        uint32_t sst = sbase + stage * STAGE_BYTES;
        #pragma unroll
        for (int tile = 0; tile < 4; tile++) {
            const __nv_bfloat16* src = tsrc[tile];
            const int rowbase = (tile < 2) ? bm : bn;
            #pragma unroll
            for (int i = 0; i < 2; i++) {
                int ci  = tid + i * 256;
                int row = ci >> 2;
                int cc  = ci & 3;
                uint32_t sdst = sst + tile * TILE_BYTES + row * TSTRIDE + cc * 16;
                const void* g = (const void*)(src + (size_t)(rowbase + row) * GK + k0 + cc * 8);
                cp_async16(sdst, g);
            }
        }
        CP_COMMIT();
    };

    const int a_row  = lane & 15;
    const int a_koff = (lane >> 4) << 3;
    const int b_row  = (lane & 7) + ((lane & 16) ? 8 : 0);
    const int b_koff = (lane & 8) ? 8 : 0;

    const int NIT = GK / BKK;                 // 32
    load_stage(0, 0);
    load_stage(1, BKK);

    for (int it = 0; it < NIT; it++) {
        if (it + 1 < NIT) { CP_WAIT(1); } else { CP_WAIT(0); }
        __syncthreads();
        if (it + 2 < NIT) load_stage((it + 2) % NSTAGE, (it + 2) * BKK);

        const uint32_t sst  = sbase + (it % NSTAGE) * STAGE_BYTES;
        const uint32_t sAh = sst;
        const uint32_t sAl = sst + TILE_BYTES;
        const uint32_t sBh = sst + 2 * TILE_BYTES;
        const uint32_t sBl = sst + 3 * TILE_BYTES;

        #pragma unroll
        for (int ks = 0; ks < 2; ks++) {
            const int kb = ks * 16;
            uint32_t ah[4][4], al[4][4], bh[2][4], bl[2][4];
            #pragma unroll
            for (int am = 0; am < 4; am++) {
                uint32_t off = (wm * 64 + am * 16 + a_row) * TSTRIDE + (kb + a_koff) * 2;
                ldsm4(ah[am][0], ah[am][1], ah[am][2], ah[am][3], sAh + off);
                ldsm4(al[am][0], al[am][1], al[am][2], al[am][3], sAl + off);
            }
            #pragma unroll
            for (int p = 0; p < 2; p++) {
                uint32_t off = (wn * 32 + p * 16 + b_row) * TSTRIDE + (kb + b_koff) * 2;
                ldsm4(bh[p][0], bh[p][1], bh[p][2], bh[p][3], sBh + off);
                ldsm4(bl[p][0], bl[p][1], bl[p][2], bl[p][3], sBl + off);
            }
            #pragma unroll
            for (int am = 0; am < 4; am++) {
                #pragma unroll
                for (int an = 0; an < 4; an++) {
                    const int p = an >> 1, q = (an & 1) * 2;
                    float* c = acc[am][an];
                    mma16816(c, ah[am], bh[p][q], bh[p][q + 1]);
                    mma16816(c, ah[am], bl[p][q], bl[p][q + 1]);
                    mma16816(c, al[am], bh[p][q], bh[p][q + 1]);
                }
            }
        }
    }

    const int g = lane >> 2, t4 = lane & 3;
    #pragma unroll
    for (int am = 0; am < 4; am++) {
        const int row0 = bm + wm * 64 + am * 16 + g;
        #pragma unroll
        for (int an = 0; an < 4; an++) {
            const int col = bn + wn * 32 + an * 8 + 2 * t4;
            const float* c = acc[am][an];
            const float bx = bias[col], by = bias[col + 1];
            size_t o1 = (size_t)row0 * N + col;
            size_t o2 = (size_t)(row0 + 8) * N + col;
            float2 v1 = make_float2(c[0] + bx, c[1] + by);
            float2 v2 = make_float2(c[2] + bx, c[3] + by);
            if (HOUT) {
                __half* C = (__half*)Cv;
                *(__half2*)&C[o1] = __floats2half2_rn(v1.x, v1.y);
                *(__half2*)&C[o2] = __floats2half2_rn(v2.x, v2.y);
            } else {
                float* C = (float*)Cv;
                if (RESID) {
                    float2 r1 = *(const float2*)&resid[o1];
                    float2 r2 = *(const float2*)&resid[o2];
                    v1.x += r1.x; v1.y += r1.y;
                    v2.x += r2.x; v2.y += r2.y;
                }
                *(float2*)&C[o1] = v1;
                *(float2*)&C[o2] = v2;
            }
        }
    }
}

// ---------------------------------------------------------------------------
// Flash attention, all-fp16 operands (qkv stored fp16), fp32 softmax/accum.
// CTA: 128 q-rows x (head,batch); 8 warps, warp owns 16 q-rows; 64-key tiles.
// K/V double-buffered via cp.async. Writes O as bf16 hi/lo split.
// ---------------------------------------------------------------------------
#define KPITCH 144                        // 64 fp16 = 128B + 16B pad
#define AQ_BYTES (128 * KPITCH)
#define AKV_BYTES (64 * KPITCH)
#define ATTN_SMEM (AQ_BYTES + 4 * AKV_BYTES + 2 * 192 * 4)   // 56832

__global__ __launch_bounds__(256, 1)
void attn_mma(const __half* __restrict__ qkv, const float* __restrict__ rpb,
              __nv_bfloat16* __restrict__ OH, __nv_bfloat16* __restrict__ OL)
{
    extern __shared__ char asmem[];
    const uint32_t sQ = smem_u32(asmem);
    const uint32_t sKb[2] = { sQ + AQ_BYTES, sQ + AQ_BYTES + 2 * AKV_BYTES };
    const uint32_t sVb[2] = { sKb[0] + AKV_BYTES, sKb[1] + AKV_BYTES };
    float* rpb0 = (float*)(asmem + AQ_BYTES + 4 * AKV_BYTES);
    float* rpb1 = rpb0 + 192;

    const int qt = gridDim.x - 1 - blockIdx.x;   // heavy tiles first
    const int h  = blockIdx.y;
    const int b  = blockIdx.z;
    const int tid  = threadIdx.x;
    const int wid  = tid >> 5;
    const int lane = tid & 31;
    const int g  = lane >> 2;
    const int t4 = lane & 3;
    const int qbase = qt * 128;

    // ---- Q tile via cp.async (group 0) ----
    #pragma unroll
    for (int l = 0; l < 4; l++) {
        int idx = tid + l * 256;          // 0..1023
        int row = idx >> 3;
        int ch  = idx & 7;
        cp_async16(sQ + row * KPITCH + ch * 16,
                   qkv + ((size_t)(b * S + qbase + row)) * 3 * D + h * HD + ch * 8);
    }
    CP_COMMIT();

    auto load_kv = [&](int buf, int kbase, float* rp) {
        #pragma unroll
        for (int l = 0; l < 2; l++) {
            int idx = tid + l * 256;      // 0..511
            int row = idx >> 3;
            int ch  = idx & 7;
            size_t base = ((size_t)(b * S + kbase + row)) * 3 * D + h * HD + ch * 8;
            cp_async16(sKb[buf] + row * KPITCH + ch * 16, qkv + base + D);
            cp_async16(sVb[buf] + row * KPITCH + ch * 16, qkv + base + 2 * D);
        }
        CP_COMMIT();
        if (tid < 192) {
            int ridx = (kbase - qbase - 127) + tid + (S - 1);
            rp[tid] = (ridx >= 0 && ridx <= 2 * S - 2) ? rpb[ridx * H + h] : 0.f;
        }
    };

    load_kv(0, 0, rpb0);                  // group 1

    // wait for Q (leave kv0 in flight), preload Q fragments
    CP_WAIT(1);
    __syncthreads();
    const int a_row  = lane & 15;
    const int a_koff = (lane >> 4) << 3;
    uint32_t qf[4][4];
    #pragma unroll
    for (int kc = 0; kc < 4; kc++) {
        uint32_t off = (wid * 16 + a_row) * KPITCH + (kc * 16 + a_koff) * 2;
        ldsm4(qf[kc][0], qf[kc][1], qf[kc][2], qf[kc][3], sQ + off);
    }

    float o_acc[8][4];
    #pragma unroll
    for (int i = 0; i < 8; i++)
        #pragma unroll
        for (int j = 0; j < 4; j++) o_acc[i][j] = 0.f;
    float mrow[2] = { -1e30f, -1e30f };
    float lrow[2] = { 0.f, 0.f };

    const int b_row  = (lane & 7) + ((lane & 16) ? 8 : 0);
    const int b_koff = (lane & 8) ? 8 : 0;
    const int li0 = wid * 16 + g;
    const int tq  = lane >> 3;

    const int nkt = 2 * qt + 2;
    for (int kt = 0; kt < nkt; kt++) {
        const int kbase = kt * 64;
        const int buf = kt & 1;
        if (kt + 1 < nkt) load_kv(1 - buf, (kt + 1) * 64, buf ? rpb0 : rpb1);
        if (kt + 1 < nkt) { CP_WAIT(1); } else { CP_WAIT(0); }
        __syncthreads();

        const uint32_t sK = sKb[buf];
        const uint32_t sV = sVb[buf];
        const float* rpbs = buf ? rpb1 : rpb0;

        // ---- S = Q K^T ----
        float sc[8][4];
        #pragma unroll
        for (int i = 0; i < 8; i++)
            #pragma unroll
            for (int j = 0; j < 4; j++) sc[i][j] = 0.f;
        #pragma unroll
        for (int kc = 0; kc < 4; kc++) {
            #pragma unroll
            for (int nb = 0; nb < 4; nb++) {
                uint32_t k0, k1, k2, k3;
                ldsm4(k0, k1, k2, k3,
                      sK + (nb * 16 + b_row) * KPITCH + (kc * 16 + b_koff) * 2);
                mma16816h(sc[nb * 2],     qf[kc], k0, k1);
                mma16816h(sc[nb * 2 + 1], qf[kc], k2, k3);
            }
        }

        // ---- scale + rpb + causal; row max ----
        float tmax0 = -1e30f, tmax1 = -1e30f;
        #pragma unroll
        for (int blk = 0; blk < 8; blk++) {
            int lj = blk * 8 + 2 * t4;
            int d00 = lj - li0 + 127;
            bool in0 = (kbase + lj)     <= (qbase + li0);
            bool in1 = (kbase + lj + 1) <= (qbase + li0);
            bool in2 = (kbase + lj)     <= (qbase + li0 + 8);
            bool in3 = (kbase + lj + 1) <= (qbase + li0 + 8);
            float v0 = fmaf(sc[blk][0], SM_SCALE, rpbs[d00]);
            float v1 = fmaf(sc[blk][1], SM_SCALE, rpbs[d00 + 1]);
            float v2 = fmaf(sc[blk][2], SM_SCALE, rpbs[d00 - 8]);
            float v3 = fmaf(sc[blk][3], SM_SCALE, rpbs[d00 - 7]);
            v0 = in0 ? v0 : -1e30f;
            v1 = in1 ? v1 : -1e30f;
            v2 = in2 ? v2 : -1e30f;
            v3 = in3 ? v3 : -1e30f;
            sc[blk][0] = v0; sc[blk][1] = v1; sc[blk][2] = v2; sc[blk][3] = v3;
            tmax0 = fmaxf(tmax0, fmaxf(v0, v1));
            tmax1 = fmaxf(tmax1, fmaxf(v2, v3));
        }
        tmax0 = fmaxf(tmax0, __shfl_xor_sync(0xffffffffu, tmax0, 1));
        tmax0 = fmaxf(tmax0, __shfl_xor_sync(0xffffffffu, tmax0, 2));
        tmax1 = fmaxf(tmax1, __shfl_xor_sync(0xffffffffu, tmax1, 1));
        tmax1 = fmaxf(tmax1, __shfl_xor_sync(0xffffffffu, tmax1, 2));

        float mn0 = fmaxf(mrow[0], tmax0);
        float mn1 = fmaxf(mrow[1], tmax1);
        float alpha0 = fexp(mrow[0] - mn0);
        float alpha1 = fexp(mrow[1] - mn1);
        mrow[0] = mn0; mrow[1] = mn1;

        // ---- p = exp(s-m) -> fp16 A fragments; row sums ----
        float rs0 = 0.f, rs1 = 0.f;
        uint32_t pf[8][2];
        #pragma unroll
        for (int blk = 0; blk < 8; blk++) {
            float p0 = fexp(sc[blk][0] - mn0);
            float p1 = fexp(sc[blk][1] - mn0);
            float p2 = fexp(sc[blk][2] - mn1);
            float p3 = fexp(sc[blk][3] - mn1);
            rs0 += p0 + p1;
            rs1 += p2 + p3;
            pf[blk][0] = pack_h2(p0, p1);
            pf[blk][1] = pack_h2(p2, p3);
        }
        rs0 += __shfl_xor_sync(0xffffffffu, rs0, 1);
        rs0 += __shfl_xor_sync(0xffffffffu, rs0, 2);
        rs1 += __shfl_xor_sync(0xffffffffu, rs1, 1);
        rs1 += __shfl_xor_sync(0xffffffffu, rs1, 2);
        lrow[0] = lrow[0] * alpha0 + rs0;
        lrow[1] = lrow[1] * alpha1 + rs1;

        #pragma unroll
        for (int blk = 0; blk < 8; blk++) {
            o_acc[blk][0] *= alpha0; o_acc[blk][1] *= alpha0;
            o_acc[blk][2] *= alpha1; o_acc[blk][3] *= alpha1;
        }

        // ---- O += P V ----
        #pragma unroll
        for (int kc = 0; kc < 4; kc++) {
            uint32_t aP[4] = { pf[2 * kc][0], pf[2 * kc][1],
                               pf[2 * kc + 1][0], pf[2 * kc + 1][1] };
            #pragma unroll
            for (int nb = 0; nb < 4; nb++) {
                uint32_t roff = (kc * 16 + (tq & 1) * 8 + (lane & 7)) * KPITCH
                              + (nb * 16 + (tq >> 1) * 8) * 2;
                uint32_t v0, v1, v2, v3;
                ldsm4t(v0, v1, v2, v3, sV + roff);
                mma16816h(o_acc[nb * 2],     aP, v0, v1);
                mma16816h(o_acc[nb * 2 + 1], aP, v2, v3);
            }
        }
        __syncthreads();   // protect buf before next overwrite
    }

    // ---- epilogue: normalize, bf16 hi/lo split, store ----
    const float inv0 = 1.f / lrow[0];
    const float inv1 = 1.f / lrow[1];
    const size_t r0 = (size_t)(b * S + qbase + wid * 16 + g) * D + h * HD;
    const size_t r1 = r0 + 8 * D;
    #pragma unroll
    for (int blk = 0; blk < 8; blk++) {
        int col = blk * 8 + 2 * t4;
        float a0 = o_acc[blk][0] * inv0, a1 = o_acc[blk][1] * inv0;
        float a2 = o_acc[blk][2] * inv1, a3 = o_acc[blk][3] * inv1;
        __nv_bfloat16 h0 = __float2bfloat16(a0), h1 = __float2bfloat16(a1);
        __nv_bfloat16 h2 = __float2bfloat16(a2), h3 = __float2bfloat16(a3);
        __nv_bfloat162 hh0; hh0.x = h0; hh0.y = h1;
        __nv_bfloat162 hh1; hh1.x = h2; hh1.y = h3;
        __nv_bfloat162 ll0 = __floats2bfloat162_rn(a0 - __bfloat162float(h0),
                                                   a1 - __bfloat162float(h1));
        __nv_bfloat162 ll1 = __floats2bfloat162_rn(a2 - __bfloat162float(h2),
                                                   a3 - __bfloat162float(h3));
        *(__nv_bfloat162*)&OH[r0 + col] = hh0;
        *(__nv_bfloat162*)&OL[r0 + col] = ll0;
        *(__nv_bfloat162*)&OH[r1 + col] = hh1;
        *(__nv_bfloat162*)&OL[r1 + col] = ll1;
    }
}

// ---------------------------------------------------------------------------
// LayerNorm
// ---------------------------------------------------------------------------
__global__ __launch_bounds__(256)
void ln_kernel(const float* __restrict__ y, const float* __restrict__ g,
               const float* __restrict__ beta, float* __restrict__ out)
{
    const int row = blockIdx.x;
    const int t = threadIdx.x;
    const float4* yp = (const float4*)&y[(size_t)row * D];
    float4 v = yp[t];

    float s  = v.x + v.y + v.z + v.w;
    float ss = v.x * v.x + v.y * v.y + v.z * v.z + v.w * v.w;
    #pragma unroll
    for (int off = 16; off > 0; off >>= 1) {
        s  += __shfl_xor_sync(0xffffffffu, s,  off);
        ss += __shfl_xor_sync(0xffffffffu, ss, off);
    }
    __shared__ float sh[16];
    __shared__ float s_mu, s_rstd;
    const int w = t >> 5, lane = t & 31;
    if (lane == 0) { sh[w] = s; sh[8 + w] = ss; }
    __syncthreads();
    if (t == 0) {
        float S0 = 0.f, S1 = 0.f;
        #pragma unroll
        for (int x = 0; x < 8; x++) { S0 += sh[x]; S1 += sh[8 + x]; }
        float mu = S0 * (1.0f / D);
        float var = S1 * (1.0f / D) - mu * mu;
        s_mu = mu;
        s_rstd = rsqrtf(var + LN_EPS);
    }
    __syncthreads();
    const float mu = s_mu, r = s_rstd;
    float4 gv = ((const float4*)g)[t];
    float4 bv = ((const float4*)beta)[t];
    float4 ov;
    ov.x = (v.x - mu) * r * gv.x + bv.x;
    ov.y = (v.y - mu) * r * gv.y + bv.y;
    ov.z = (v.z - mu) * r * gv.z + bv.z;
    ov.w = (v.w - mu) * r * gv.w + bv.w;
    ((float4*)&out[(size_t)row * D])[t] = ov;
}

// ---------------------------------------------------------------------------
extern "C" void kernel_launch(void* const* d_in, const int* in_sizes, int n_in,
                              void* d_out, int out_size)
{
    const float* x      = (const float*)d_in[0];
    const float* W_w    = (const float*)d_in[1];
    const float* W_b    = (const float*)d_in[2];
    const float* proj_w = (const float*)d_in[3];
    const float* proj_b = (const float*)d_in[4];
    const float* ln_g   = (const float*)d_in[5];
    const float* ln_b   = (const float*)d_in[6];
    const float* rpb    = (const float*)d_in[7];
    float* out = (float*)d_out;

    float *ybuf;
    __half* qkv;
    __nv_bfloat16 *xh, *xl, *wh, *wl, *ph, *pl, *oh, *ol;
    cudaGetSymbolAddress((void**)&qkv,  g_qkv);
    cudaGetSymbolAddress((void**)&ybuf, g_y);
    cudaGetSymbolAddress((void**)&xh, g_xh);
    cudaGetSymbolAddress((void**)&xl, g_xl);
    cudaGetSymbolAddress((void**)&wh, g_wh);
    cudaGetSymbolAddress((void**)&wl, g_wl);
    cudaGetSymbolAddress((void**)&ph, g_ph);
    cudaGetSymbolAddress((void**)&pl, g_pl);
    cudaGetSymbolAddress((void**)&oh, g_oh);
    cudaGetSymbolAddress((void**)&ol, g_ol);

    cudaFuncSetAttribute(gemm_mma<false, true>,
                         cudaFuncAttributeMaxDynamicSharedMemorySize, GEMM_SMEM);
    cudaFuncSetAttribute(gemm_mma<true, false>,
                         cudaFuncAttributeMaxDynamicSharedMemorySize, GEMM_SMEM);
    cudaFuncSetAttribute(attn_mma,
                         cudaFuncAttributeMaxDynamicSharedMemorySize, ATTN_SMEM);

    // 0) bf16 hi/lo splits of inputs/weights
    split_kernel<<<(M_ROWS * D / 4 + 255) / 256, 256>>>(x, xh, xl, M_ROWS * D / 4);
    split_kernel<<<(3 * D * D / 4 + 255) / 256, 256>>>(W_w, wh, wl, 3 * D * D / 4);
    split_kernel<<<(D * D / 4 + 255) / 256, 256>>>(proj_w, ph, pl, D * D / 4);

    // 1) QKV = x @ W_w^T + W_b  -> fp16
    {
        dim3 grid(3 * D / 128, M_ROWS / 128);
        gemm_mma<false, true><<<grid, 256, GEMM_SMEM>>>(xh, xl, wh, wl, W_b,
                                                        nullptr, qkv, 3 * D);
    }
    // 2) attention -> (oh, ol) bf16 split
    {
        dim3 grid(S / 128, H, BATCH);
        attn_mma<<<grid, 256, ATTN_SMEM>>>(qkv, rpb, oh, ol);
    }
    // 3) y = o @ proj_w^T + proj_b + x
    {
        dim3 grid(D / 128, M_ROWS / 128);
        gemm_mma<true, false><<<grid, 256, GEMM_SMEM>>>(oh, ol, ph, pl, proj_b,
                                                        x, ybuf, D);
    }
    // 4) LayerNorm
    ln_kernel<<<M_ROWS, 256>>>(ybuf, ln_g, ln_b, out);
}